// round 7
// baseline (speedup 1.0000x reference)
#include <cuda_runtime.h>
#include <cuda_fp16.h>
#include <math.h>

// ---------------- problem constants ----------------
#define S_LEN    4096
#define DMODEL   1024
#define N_HEADS  16
#define HEAD_DIM 64
#define INV2048  4.8828125e-4f

// ---------------- scratch: fp16 hi + fp16 lo(x2048) planes ----------------
__device__ unsigned short g_xh[S_LEN * DMODEL];
__device__ unsigned short g_xl[S_LEN * DMODEL];
__device__ unsigned short g_qh[S_LEN * DMODEL];
__device__ unsigned short g_ql[S_LEN * DMODEL];
__device__ unsigned short g_kh[S_LEN * DMODEL];
__device__ unsigned short g_kl[S_LEN * DMODEL];
__device__ unsigned short g_vh[S_LEN * DMODEL];
__device__ unsigned short g_vl[S_LEN * DMODEL];
__device__ unsigned short g_ch[S_LEN * DMODEL];
__device__ unsigned short g_cl[S_LEN * DMODEL];
__device__ unsigned short g_Wqh[DMODEL * DMODEL];
__device__ unsigned short g_Wql[DMODEL * DMODEL];
__device__ unsigned short g_Wkh[DMODEL * DMODEL];
__device__ unsigned short g_Wkl[DMODEL * DMODEL];
__device__ unsigned short g_Wvh[DMODEL * DMODEL];
__device__ unsigned short g_Wvl[DMODEL * DMODEL];
__device__ unsigned short g_Woh[DMODEL * DMODEL];
__device__ unsigned short g_Wol[DMODEL * DMODEL];

// ---------------- small helpers ----------------
__device__ __forceinline__ unsigned smem_u32(const void* p) {
    unsigned a;
    asm("{ .reg .u64 t; cvta.to.shared.u64 t, %1; cvt.u32.u64 %0, t; }" : "=r"(a) : "l"(p));
    return a;
}
__device__ __forceinline__ void cp16(unsigned dst, const void* src) {
    asm volatile("cp.async.cg.shared.global [%0], [%1], 16;" :: "r"(dst), "l"(src));
}
__device__ __forceinline__ void ldm_x4(unsigned* r, unsigned addr) {
    asm volatile("ldmatrix.sync.aligned.m8n8.x4.shared.b16 {%0,%1,%2,%3}, [%4];"
                 : "=r"(r[0]), "=r"(r[1]), "=r"(r[2]), "=r"(r[3]) : "r"(addr));
}
__device__ __forceinline__ void ldm_x4t(unsigned* r, unsigned addr) {
    asm volatile("ldmatrix.sync.aligned.m8n8.x4.trans.shared.b16 {%0,%1,%2,%3}, [%4];"
                 : "=r"(r[0]), "=r"(r[1]), "=r"(r[2]), "=r"(r[3]) : "r"(addr));
}
// main-term MMA: fp16 inputs, fp32 accumulate
__device__ __forceinline__ void mma_f32(float* d, const unsigned* a, const unsigned* b) {
    asm volatile(
        "mma.sync.aligned.m16n8k16.row.col.f32.f16.f16.f32 "
        "{%0,%1,%2,%3}, {%4,%5,%6,%7}, {%8,%9}, {%0,%1,%2,%3};"
        : "+f"(d[0]), "+f"(d[1]), "+f"(d[2]), "+f"(d[3])
        : "r"(a[0]), "r"(a[1]), "r"(a[2]), "r"(a[3]), "r"(b[0]), "r"(b[1]));
}
// correction MMA: fp16 inputs, fp16 accumulate (hopefully 2x rate)
__device__ __forceinline__ void mma_f16(unsigned* d, const unsigned* a, const unsigned* b) {
    asm volatile(
        "mma.sync.aligned.m16n8k16.row.col.f16.f16.f16.f16 "
        "{%0,%1}, {%2,%3,%4,%5}, {%6,%7}, {%0,%1};"
        : "+r"(d[0]), "+r"(d[1])
        : "r"(a[0]), "r"(a[1]), "r"(a[2]), "r"(a[3]), "r"(b[0]), "r"(b[1]));
}
__device__ __forceinline__ unsigned packf16(float lo, float hi) {
    unsigned r;
    asm("cvt.rn.f16x2.f32 %0, %1, %2;" : "=r"(r) : "f"(hi), "f"(lo));
    return r;
}
__device__ __forceinline__ float f16lo_f(unsigned u) {
    float f; asm("{ .reg .f16 l, h; mov.b32 {l, h}, %1; cvt.f32.f16 %0, l; }" : "=f"(f) : "r"(u));
    return f;
}
__device__ __forceinline__ float f16hi_f(unsigned u) {
    float f; asm("{ .reg .f16 l, h; mov.b32 {l, h}, %1; cvt.f32.f16 %0, h; }" : "=f"(f) : "r"(u));
    return f;
}
__device__ __forceinline__ float ex2(float x) {
    float y; asm("ex2.approx.ftz.f32 %0, %1;" : "=f"(y) : "f"(x)); return y;
}
__device__ __forceinline__ float rcp(float x) {
    float y; asm("rcp.approx.ftz.f32 %0, %1;" : "=f"(y) : "f"(x)); return y;
}

// ---------------- split: fp32 -> fp16 hi + fp16 lo*2048 ----------------
__global__ __launch_bounds__(256)
void split_f16(const float* __restrict__ in, unsigned short* __restrict__ hi,
               unsigned short* __restrict__ lo)
{
    int i = (blockIdx.x * 256 + threadIdx.x) * 4;
    float4 a = *(const float4*)(in + i);
    unsigned h0 = packf16(a.x, a.y), h1 = packf16(a.z, a.w);
    unsigned l0 = packf16((a.x - f16lo_f(h0)) * 2048.f, (a.y - f16hi_f(h0)) * 2048.f);
    unsigned l1 = packf16((a.z - f16lo_f(h1)) * 2048.f, (a.w - f16hi_f(h1)) * 2048.f);
    *(uint2*)(hi + i) = make_uint2(h0, h1);
    *(uint2*)(lo + i) = make_uint2(l0, l1);
}

// ---------------- shared GEMM body (fp16 main + fp16-acc corrections) ----------------
// 128x128 tile, BK=32, 8 warps (2x4), warp tile 64x32, 2-stage cp.async, 2 CTAs/SM.
#define ROWB   80
#define PLANE  (128 * ROWB)
#define STAGE  (4 * PLANE)
#define NSTAGE 2
#define GSMEM  (NSTAGE * STAGE)
#define NCHUNK 32

__device__ __forceinline__
void gemm_body(char* smem,
               const unsigned short* __restrict__ Ah, const unsigned short* __restrict__ Al,
               const unsigned short* __restrict__ Bh, const unsigned short* __restrict__ Bl,
               const float* __restrict__ bias, int bm, int bn,
               int mode, float* __restrict__ C,
               unsigned short* __restrict__ Ch, unsigned short* __restrict__ Cl)
{
    const int t = threadIdx.x, lane = t & 31, wid = t >> 5;
    const int wm = wid >> 2, wn = wid & 3;

    float acc[4][4][4];
    unsigned acg[4][4][2];
#pragma unroll
    for (int mt = 0; mt < 4; mt++)
#pragma unroll
        for (int nt = 0; nt < 4; nt++) {
#pragma unroll
            for (int r = 0; r < 4; r++) acc[mt][nt][r] = 0.f;
            acg[mt][nt][0] = 0u; acg[mt][nt][1] = 0u;
        }

    const int r0 = t >> 2, s0 = t & 3;
    const int r1 = r0 + 64;

    const unsigned short* srcs[4] = {Ah, Al, Bh, Bl};
    const int rowbase[4] = {bm, bm, bn, bn};

#define ISSUE(cc)                                                                 \
    {                                                                             \
        char* sb = smem + ((cc) & (NSTAGE - 1)) * STAGE;                          \
        const int gk = (cc) * 32 + s0 * 8;                                        \
        _Pragma("unroll")                                                         \
        for (int pl = 0; pl < 4; pl++) {                                          \
            const unsigned short* gp = srcs[pl] + (size_t)rowbase[pl] * DMODEL + gk; \
            unsigned db = smem_u32(sb + pl * PLANE + s0 * 16);                    \
            cp16(db + r0 * ROWB, gp + (size_t)r0 * DMODEL);                       \
            cp16(db + r1 * ROWB, gp + (size_t)r1 * DMODEL);                       \
        }                                                                         \
        asm volatile("cp.async.commit_group;" ::: "memory");                      \
    }

    ISSUE(0); ISSUE(1);

    const int a_row = wm * 64 + (lane & 15);
    const unsigned a_coff = (lane >> 4) * 16;
    const int b_row = wn * 32 + (lane & 7) + ((lane >> 4) << 3);
    const unsigned b_coff = ((lane >> 3) & 1) * 16;

    for (int c = 0; c < NCHUNK; c++) {
        if (c + 1 < NCHUNK) {
            asm volatile("cp.async.wait_group 1;" ::: "memory");
        } else {
            asm volatile("cp.async.wait_group 0;" ::: "memory");
        }
        __syncthreads();

        char* sb = smem + (c & (NSTAGE - 1)) * STAGE;
        const unsigned sAh = smem_u32(sb);
        const unsigned sAl = sAh + PLANE;
        const unsigned sBh = sAh + 2 * PLANE;
        const unsigned sBl = sAh + 3 * PLANE;

#pragma unroll
        for (int ks = 0; ks < 2; ks++) {
            const unsigned ka = ks * 32;
            unsigned bh[2][4], bl[2][4];
#pragma unroll
            for (int pr = 0; pr < 2; pr++) {
                unsigned off = (unsigned)((b_row + pr * 16) * ROWB) + ka + b_coff;
                ldm_x4(bh[pr], sBh + off);
                ldm_x4(bl[pr], sBl + off);
            }
#pragma unroll
            for (int mt = 0; mt < 4; mt++) {
                unsigned ah[4], al[4];
                unsigned off = (unsigned)((a_row + mt * 16) * ROWB) + ka + a_coff;
                ldm_x4(ah, sAh + off);
                ldm_x4(al, sAl + off);
#pragma unroll
                for (int pr = 0; pr < 2; pr++)
#pragma unroll
                    for (int half = 0; half < 2; half++) {
                        const int nt = pr * 2 + half;
                        mma_f32(acc[mt][nt], ah, &bh[pr][half * 2]);
                        mma_f16(acg[mt][nt], ah, &bl[pr][half * 2]);
                        mma_f16(acg[mt][nt], al, &bh[pr][half * 2]);
                    }
            }
        }
        __syncthreads();
        if (c + 2 < NCHUNK) ISSUE(c + 2);
    }
#undef ISSUE

    // ---- epilogue: combine main + corr/2048, add bias ----
    const int er = lane >> 2, ec = (lane & 3) * 2;
#pragma unroll
    for (int mt = 0; mt < 4; mt++) {
        const int row = bm + wm * 64 + mt * 16 + er;
#pragma unroll
        for (int nt = 0; nt < 4; nt++) {
            const int col = bn + wn * 32 + nt * 8 + ec;
            const float b0 = bias[col], b1 = bias[col + 1];
            float v0 = acc[mt][nt][0] + f16lo_f(acg[mt][nt][0]) * INV2048 + b0;
            float v1 = acc[mt][nt][1] + f16hi_f(acg[mt][nt][0]) * INV2048 + b1;
            float v2 = acc[mt][nt][2] + f16lo_f(acg[mt][nt][1]) * INV2048 + b0;
            float v3 = acc[mt][nt][3] + f16hi_f(acg[mt][nt][1]) * INV2048 + b1;
            if (mode == 0) {
                *(float2*)&C[(size_t)row * DMODEL + col] = make_float2(v0, v1);
                *(float2*)&C[(size_t)(row + 8) * DMODEL + col] = make_float2(v2, v3);
            } else {
                unsigned hp0 = packf16(v0, v1);
                unsigned lp0 = packf16((v0 - f16lo_f(hp0)) * 2048.f, (v1 - f16hi_f(hp0)) * 2048.f);
                unsigned hp1 = packf16(v2, v3);
                unsigned lp1 = packf16((v2 - f16lo_f(hp1)) * 2048.f, (v3 - f16hi_f(hp1)) * 2048.f);
                *(unsigned*)&Ch[(size_t)row * DMODEL + col] = hp0;
                *(unsigned*)&Cl[(size_t)row * DMODEL + col] = lp0;
                *(unsigned*)&Ch[(size_t)(row + 8) * DMODEL + col] = hp1;
                *(unsigned*)&Cl[(size_t)(row + 8) * DMODEL + col] = lp1;
            }
        }
    }
}

__global__ __launch_bounds__(256, 2)
void gemm_qkv(const float* __restrict__ bq, const float* __restrict__ bk,
              const float* __restrict__ bv)
{
    extern __shared__ char smem[];
    const int which = blockIdx.x >> 3;
    const int bn = (blockIdx.x & 7) * 128;
    const int bm = blockIdx.y * 128;
    const unsigned short* Bh = (which == 0) ? g_Wqh : (which == 1) ? g_Wkh : g_Wvh;
    const unsigned short* Bl = (which == 0) ? g_Wql : (which == 1) ? g_Wkl : g_Wvl;
    const float* bias = (which == 0) ? bq : (which == 1) ? bk : bv;
    unsigned short* Ch = (which == 0) ? g_qh : (which == 1) ? g_kh : g_vh;
    unsigned short* Cl = (which == 0) ? g_ql : (which == 1) ? g_kl : g_vl;
    gemm_body(smem, g_xh, g_xl, Bh, Bl, bias, bm, bn, 1, nullptr, Ch, Cl);
}

__global__ __launch_bounds__(256, 2)
void gemm_out(const float* __restrict__ bo, float* __restrict__ out)
{
    extern __shared__ char smem[];
    gemm_body(smem, g_ch, g_cl, g_Woh, g_Wol, bo,
              blockIdx.y * 128, blockIdx.x * 128, 0, out, nullptr, nullptr);
}

// ---------------- tensorized sliding-window attention ----------------
#define AT_Q   64
#define AT_K   192
#define AROWB  144
#define A_SQH  0
#define A_SQL  (64 * AROWB)
#define A_SKH  (2 * 64 * AROWB)
#define A_SKL  (A_SKH + AT_K * AROWB)
#define A_SVH  (A_SKL + AT_K * AROWB)
#define A_SVL  (A_SVH + AT_K * AROWB)
#define A_SMEM (A_SVL + AT_K * AROWB)       // 129024

__global__ __launch_bounds__(128)
void attn_mma()
{
    extern __shared__ char smem[];
    const unsigned sb = smem_u32(smem);
    const int t = threadIdx.x, lane = t & 31, w = t >> 5;
    const int h = blockIdx.y;
    const int q0 = blockIdx.x * AT_Q;
    const int j0 = q0 - 64;
    const int col = h * HEAD_DIM;

#pragma unroll
    for (int i = 0; i < 4; i++) {
        int idx = t + i * 128;
        int r = idx >> 3, sg = idx & 7;
        size_t go = (size_t)(q0 + r) * DMODEL + col + sg * 8;
        *(uint4*)(smem + A_SQH + r * AROWB + sg * 16) = *(const uint4*)(g_qh + go);
        *(uint4*)(smem + A_SQL + r * AROWB + sg * 16) = *(const uint4*)(g_ql + go);
    }
#pragma unroll
    for (int i = 0; i < 12; i++) {
        int idx = t + i * 128;
        int r = idx >> 3, sg = idx & 7;
        int j = j0 + r;
        uint4 kh = make_uint4(0,0,0,0), kl = kh, vh = kh, vl = kh;
        if ((unsigned)j < (unsigned)S_LEN) {
            size_t go = (size_t)j * DMODEL + col + sg * 8;
            kh = *(const uint4*)(g_kh + go);
            kl = *(const uint4*)(g_kl + go);
            vh = *(const uint4*)(g_vh + go);
            vl = *(const uint4*)(g_vl + go);
        }
        unsigned so = r * AROWB + sg * 16;
        *(uint4*)(smem + A_SKH + so) = kh;
        *(uint4*)(smem + A_SKL + so) = kl;
        *(uint4*)(smem + A_SVH + so) = vh;
        *(uint4*)(smem + A_SVL + so) = vl;
    }
    __syncthreads();

    // ---- S = Q K^T: main fp32, corrections fp16-acc ----
    float sc[24][4];
    unsigned sg16[24][2];
#pragma unroll
    for (int nt = 0; nt < 24; nt++) {
#pragma unroll
        for (int r = 0; r < 4; r++) sc[nt][r] = 0.f;
        sg16[nt][0] = 0u; sg16[nt][1] = 0u;
    }

    const unsigned a_base = (unsigned)((w * 16 + (lane & 15)) * AROWB) + ((lane >> 4) << 4);
    const int b_lrow = (lane & 7) + ((lane >> 4) << 3);
    const unsigned b_coff = ((lane >> 3) & 1) << 4;

#pragma unroll
    for (int kc = 0; kc < 4; kc++) {
        unsigned ah[4], al[4];
        ldm_x4(ah, sb + A_SQH + a_base + kc * 32);
        ldm_x4(al, sb + A_SQL + a_base + kc * 32);
#pragma unroll
        for (int pr = 0; pr < 12; pr++) {
            unsigned bh[4], bl[4];
            unsigned off = (unsigned)((pr * 16 + b_lrow) * AROWB) + kc * 32 + b_coff;
            ldm_x4(bh, sb + A_SKH + off);
            ldm_x4(bl, sb + A_SKL + off);
#pragma unroll
            for (int half = 0; half < 2; half++) {
                const int nt = pr * 2 + half;
                mma_f32(sc[nt], ah, &bh[half * 2]);
                mma_f16(sg16[nt], ah, &bl[half * 2]);
                mma_f16(sg16[nt], al, &bh[half * 2]);
            }
        }
    }

    // ---- combine + mask + softmax ----
    const int er = lane >> 2, ec = (lane & 3) * 2;
    const int qa = w * 16 + er, qb = qa + 8;
    const float SC = 0.125f * 1.44269504088896f;
    float m0 = -1e30f, m1 = -1e30f;
#pragma unroll
    for (int nt = 0; nt < 24; nt++) {
        int kl = nt * 8 + ec;
        int j  = j0 + kl;
        float u0 = sc[nt][0] + f16lo_f(sg16[nt][0]) * INV2048;
        float u1 = sc[nt][1] + f16hi_f(sg16[nt][0]) * INV2048;
        float u2 = sc[nt][2] + f16lo_f(sg16[nt][1]) * INV2048;
        float u3 = sc[nt][3] + f16hi_f(sg16[nt][1]) * INV2048;
        bool v00 = ((unsigned)(kl     - qa) <= 128u) && ((unsigned)j       < (unsigned)S_LEN);
        bool v01 = ((unsigned)(kl + 1 - qa) <= 128u) && ((unsigned)(j + 1) < (unsigned)S_LEN);
        bool v10 = ((unsigned)(kl     - qb) <= 128u) && ((unsigned)j       < (unsigned)S_LEN);
        bool v11 = ((unsigned)(kl + 1 - qb) <= 128u) && ((unsigned)(j + 1) < (unsigned)S_LEN);
        sc[nt][0] = v00 ? u0 * SC : -1e30f;
        sc[nt][1] = v01 ? u1 * SC : -1e30f;
        sc[nt][2] = v10 ? u2 * SC : -1e30f;
        sc[nt][3] = v11 ? u3 * SC : -1e30f;
        m0 = fmaxf(m0, fmaxf(sc[nt][0], sc[nt][1]));
        m1 = fmaxf(m1, fmaxf(sc[nt][2], sc[nt][3]));
    }
    m0 = fmaxf(m0, __shfl_xor_sync(0xffffffffu, m0, 1));
    m0 = fmaxf(m0, __shfl_xor_sync(0xffffffffu, m0, 2));
    m1 = fmaxf(m1, __shfl_xor_sync(0xffffffffu, m1, 1));
    m1 = fmaxf(m1, __shfl_xor_sync(0xffffffffu, m1, 2));

    float s0 = 0.f, s1 = 0.f;
#pragma unroll
    for (int nt = 0; nt < 24; nt++) {
        sc[nt][0] = ex2(sc[nt][0] - m0);
        sc[nt][1] = ex2(sc[nt][1] - m0);
        sc[nt][2] = ex2(sc[nt][2] - m1);
        sc[nt][3] = ex2(sc[nt][3] - m1);
        s0 += sc[nt][0] + sc[nt][1];
        s1 += sc[nt][2] + sc[nt][3];
    }
    s0 += __shfl_xor_sync(0xffffffffu, s0, 1);
    s0 += __shfl_xor_sync(0xffffffffu, s0, 2);
    s1 += __shfl_xor_sync(0xffffffffu, s1, 1);
    s1 += __shfl_xor_sync(0xffffffffu, s1, 2);
    const float inv0 = rcp(s0), inv1 = rcp(s1);

    // ---- O = P V: main fp32, corrections fp16-acc ----
    float oa[8][4];
    unsigned og[8][2];
#pragma unroll
    for (int nt = 0; nt < 8; nt++) {
#pragma unroll
        for (int r = 0; r < 4; r++) oa[nt][r] = 0.f;
        og[nt][0] = 0u; og[nt][1] = 0u;
    }

#pragma unroll
    for (int kc = 0; kc < 12; kc++) {
        unsigned ph[4], pl[4];
        ph[0] = packf16(sc[2 * kc][0],     sc[2 * kc][1]);
        ph[1] = packf16(sc[2 * kc][2],     sc[2 * kc][3]);
        ph[2] = packf16(sc[2 * kc + 1][0], sc[2 * kc + 1][1]);
        ph[3] = packf16(sc[2 * kc + 1][2], sc[2 * kc + 1][3]);
        pl[0] = packf16((sc[2 * kc][0]     - f16lo_f(ph[0])) * 2048.f, (sc[2 * kc][1]     - f16hi_f(ph[0])) * 2048.f);
        pl[1] = packf16((sc[2 * kc][2]     - f16lo_f(ph[1])) * 2048.f, (sc[2 * kc][3]     - f16hi_f(ph[1])) * 2048.f);
        pl[2] = packf16((sc[2 * kc + 1][0] - f16lo_f(ph[2])) * 2048.f, (sc[2 * kc + 1][1] - f16hi_f(ph[2])) * 2048.f);
        pl[3] = packf16((sc[2 * kc + 1][2] - f16lo_f(ph[3])) * 2048.f, (sc[2 * kc + 1][3] - f16hi_f(ph[3])) * 2048.f);
#pragma unroll
        for (int dt = 0; dt < 4; dt++) {
            unsigned vh[4], vl[4];
            unsigned voff = (unsigned)((kc * 16 + (lane & 15)) * AROWB) + dt * 32 + ((lane >> 4) << 4);
            ldm_x4t(vh, sb + A_SVH + voff);
            ldm_x4t(vl, sb + A_SVL + voff);
            mma_f32(oa[2 * dt],     ph, &vh[0]);
            mma_f16(og[2 * dt],     ph, &vl[0]);
            mma_f16(og[2 * dt],     pl, &vh[0]);
            mma_f32(oa[2 * dt + 1], ph, &vh[2]);
            mma_f16(og[2 * dt + 1], ph, &vl[2]);
            mma_f16(og[2 * dt + 1], pl, &vh[2]);
        }
    }

    // ---- normalize + write ctx as fp16 hi/lo ----
    const int row0 = q0 + w * 16 + er;
#pragma unroll
    for (int nt = 0; nt < 8; nt++) {
        const int oc = col + nt * 8 + ec;
        float v0 = (oa[nt][0] + f16lo_f(og[nt][0]) * INV2048) * inv0;
        float v1 = (oa[nt][1] + f16hi_f(og[nt][0]) * INV2048) * inv0;
        float v2 = (oa[nt][2] + f16lo_f(og[nt][1]) * INV2048) * inv1;
        float v3 = (oa[nt][3] + f16hi_f(og[nt][1]) * INV2048) * inv1;
        unsigned hp0 = packf16(v0, v1);
        unsigned lp0 = packf16((v0 - f16lo_f(hp0)) * 2048.f, (v1 - f16hi_f(hp0)) * 2048.f);
        unsigned hp1 = packf16(v2, v3);
        unsigned lp1 = packf16((v2 - f16lo_f(hp1)) * 2048.f, (v3 - f16hi_f(hp1)) * 2048.f);
        *(unsigned*)&g_ch[(size_t)row0 * DMODEL + oc] = hp0;
        *(unsigned*)&g_cl[(size_t)row0 * DMODEL + oc] = lp0;
        *(unsigned*)&g_ch[(size_t)(row0 + 8) * DMODEL + oc] = hp1;
        *(unsigned*)&g_cl[(size_t)(row0 + 8) * DMODEL + oc] = lp1;
    }
}

// ---------------- launch ----------------
extern "C" void kernel_launch(void* const* d_in, const int* in_sizes, int n_in,
                              void* d_out, int out_size)
{
    const float* x  = (const float*)d_in[0];
    const float* Wq = (const float*)d_in[1];
    const float* bq = (const float*)d_in[2];
    const float* Wk = (const float*)d_in[3];
    const float* bk = (const float*)d_in[4];
    const float* Wv = (const float*)d_in[5];
    const float* bv = (const float*)d_in[6];
    const float* Wo = (const float*)d_in[7];
    const float* bo = (const float*)d_in[8];
    float* out = (float*)d_out;

    unsigned short *xh, *xl;
    unsigned short *wqh, *wql, *wkh, *wkl, *wvh, *wvl, *woh, *wol;
    cudaGetSymbolAddress((void**)&xh, g_xh);   cudaGetSymbolAddress((void**)&xl, g_xl);
    cudaGetSymbolAddress((void**)&wqh, g_Wqh); cudaGetSymbolAddress((void**)&wql, g_Wql);
    cudaGetSymbolAddress((void**)&wkh, g_Wkh); cudaGetSymbolAddress((void**)&wkl, g_Wkl);
    cudaGetSymbolAddress((void**)&wvh, g_Wvh); cudaGetSymbolAddress((void**)&wvl, g_Wvl);
    cudaGetSymbolAddress((void**)&woh, g_Woh); cudaGetSymbolAddress((void**)&wol, g_Wol);

    cudaFuncSetAttribute(gemm_qkv, cudaFuncAttributeMaxDynamicSharedMemorySize, GSMEM);
    cudaFuncSetAttribute(gemm_out, cudaFuncAttributeMaxDynamicSharedMemorySize, GSMEM);
    cudaFuncSetAttribute(attn_mma, cudaFuncAttributeMaxDynamicSharedMemorySize, A_SMEM);

    const int nx = S_LEN * DMODEL;
    const int nw = DMODEL * DMODEL;

    split_f16<<<nx / 1024, 256>>>(x,  xh,  xl);
    split_f16<<<nw / 1024, 256>>>(Wq, wqh, wql);
    split_f16<<<nw / 1024, 256>>>(Wk, wkh, wkl);
    split_f16<<<nw / 1024, 256>>>(Wv, wvh, wvl);
    split_f16<<<nw / 1024, 256>>>(Wo, woh, wol);

    dim3 gq(24, 32);                       // fused Q,K,V
    gemm_qkv<<<gq, 256, GSMEM>>>(bq, bk, bv);

    dim3 ga(S_LEN / AT_Q, N_HEADS);        // (64, 16)
    attn_mma<<<ga, 128, A_SMEM>>>();

    dim3 go(8, 32);
    gemm_out<<<go, 256, GSMEM>>>(bo, out);
}